// round 1
// baseline (speedup 1.0000x reference)
#include <cuda_runtime.h>

#define NN 524288
#define EE 4194304
#define BB 4096
#define HH 32
#define KK 30
#define CAP 512
#define EPSF 1e-5f

// ---------------- scratch (device globals; no allocation allowed) ----------
__device__ int   g_deg[NN];
__device__ float g_dinv[NN];
__device__ float g_h[(size_t)NN * HH];
__device__ float g_agg[(size_t)NN * HH];
__device__ int   g_cnt[BB];
__device__ int   g_start[BB];
__device__ float g_pooled[(size_t)BB * KK * HH];

// ---------------- small setup kernels --------------------------------------
__global__ void k_zero() {
    int i = blockIdx.x * blockDim.x + threadIdx.x;
    if (i < NN) g_deg[i] = 0;
    if (i < BB) g_cnt[i] = 0;
}

__global__ void k_degcnt(const int* __restrict__ dst, const int* __restrict__ batch) {
    int i = blockIdx.x * blockDim.x + threadIdx.x;
    if (i < EE) atomicAdd(&g_deg[dst[i]], 1);
    if (i < NN) atomicAdd(&g_cnt[batch[i]], 1);
}

__global__ void k_dinv() {
    int i = blockIdx.x * blockDim.x + threadIdx.x;
    if (i < NN) g_dinv[i] = rsqrtf((float)g_deg[i] + 1.0f);
}

// exclusive scan of g_cnt (4096) -> g_start
__global__ void k_scan() {
    __shared__ int ssum[1024];
    int t = threadIdx.x;
    int base = t * 4;
    int c0 = g_cnt[base + 0], c1 = g_cnt[base + 1], c2 = g_cnt[base + 2], c3 = g_cnt[base + 3];
    ssum[t] = c0 + c1 + c2 + c3;
    __syncthreads();
    if (t == 0) {
        int acc = 0;
        for (int i = 0; i < 1024; i++) { int v = ssum[i]; ssum[i] = acc; acc += v; }
    }
    __syncthreads();
    int acc = ssum[t];
    g_start[base + 0] = acc; acc += c0;
    g_start[base + 1] = acc; acc += c1;
    g_start[base + 2] = acc; acc += c2;
    g_start[base + 3] = acc;
}

// ---------------- fused (BN+ReLU of prev layer) + GEMM + agg init ----------
// layer 0: x = emb[x_z];  layer>0: x = relu(bn_{layer-1}(agg))
// h = x @ Wc[layer];  agg = h * dinv^2 + bc[layer]
__global__ void __launch_bounds__(256) k_gemm(
    int layer,
    const float* __restrict__ Wc, const float* __restrict__ bcp,
    const float* __restrict__ gamma, const float* __restrict__ beta,
    const float* __restrict__ rmean, const float* __restrict__ rvar,
    const float* __restrict__ emb, const int* __restrict__ xz)
{
    __shared__ float Ws[HH * HH];
    __shared__ float ssc[HH], ssh[HH], sbc[HH];
    int t = threadIdx.x;
    for (int i = t; i < HH * HH; i += 256) Ws[i] = Wc[layer * HH * HH + i];
    if (t < HH) {
        sbc[t] = bcp[layer * HH + t];
        if (layer > 0) {
            int o = (layer - 1) * HH + t;
            float s = gamma[o] * rsqrtf(rvar[o] + EPSF);
            ssc[t] = s;
            ssh[t] = beta[o] - rmean[o] * s;
        }
    }
    __syncthreads();

    int n = blockIdx.x * 256 + t;   // grid covers NN exactly
    float xin[HH];
    if (layer == 0) {
        const float4* ep = (const float4*)(emb + (size_t)xz[n] * HH);
#pragma unroll
        for (int q = 0; q < 8; q++) {
            float4 v = ep[q];
            xin[4 * q + 0] = v.x; xin[4 * q + 1] = v.y;
            xin[4 * q + 2] = v.z; xin[4 * q + 3] = v.w;
        }
    } else {
        const float4* ap = (const float4*)(g_agg + (size_t)n * HH);
#pragma unroll
        for (int q = 0; q < 8; q++) {
            float4 v = ap[q];
            xin[4 * q + 0] = fmaxf(fmaf(v.x, ssc[4 * q + 0], ssh[4 * q + 0]), 0.f);
            xin[4 * q + 1] = fmaxf(fmaf(v.y, ssc[4 * q + 1], ssh[4 * q + 1]), 0.f);
            xin[4 * q + 2] = fmaxf(fmaf(v.z, ssc[4 * q + 2], ssh[4 * q + 2]), 0.f);
            xin[4 * q + 3] = fmaxf(fmaf(v.w, ssc[4 * q + 3], ssh[4 * q + 3]), 0.f);
        }
    }

    float out[HH];
#pragma unroll
    for (int j = 0; j < HH; j++) out[j] = 0.f;
#pragma unroll
    for (int k = 0; k < HH; k++) {
        float xk = xin[k];
#pragma unroll
        for (int j = 0; j < HH; j++) out[j] = fmaf(xk, Ws[k * HH + j], out[j]);
    }

    float dn = g_dinv[n];
    float sn = dn * dn;
    float4* hp  = (float4*)(g_h   + (size_t)n * HH);
    float4* ap2 = (float4*)(g_agg + (size_t)n * HH);
#pragma unroll
    for (int q = 0; q < 8; q++) {
        float4 hv;
        hv.x = out[4 * q + 0]; hv.y = out[4 * q + 1];
        hv.z = out[4 * q + 2]; hv.w = out[4 * q + 3];
        hp[q] = hv;
        float4 av;
        av.x = fmaf(out[4 * q + 0], sn, sbc[4 * q + 0]);
        av.y = fmaf(out[4 * q + 1], sn, sbc[4 * q + 1]);
        av.z = fmaf(out[4 * q + 2], sn, sbc[4 * q + 2]);
        av.w = fmaf(out[4 * q + 3], sn, sbc[4 * q + 3]);
        ap2[q] = av;
    }
}

// ---------------- edge scatter: agg[dst] += h[src] * dinv[src]*dinv[dst] ---
// 8 threads per edge, float4 each; vectorized L2 reduction (sm_90+).
__global__ void __launch_bounds__(256) k_edge(const int* __restrict__ src,
                                              const int* __restrict__ dst) {
    int tid = blockIdx.x * 256 + threadIdx.x;  // grid covers EE*8 exactly
    int e = tid >> 3;
    int p = tid & 7;
    int s = src[e], d = dst[e];
    float w = g_dinv[s] * g_dinv[d];
    const float4* hp = (const float4*)(g_h + (size_t)s * HH);
    float4 v = hp[p];
    float* ap = g_agg + (size_t)d * HH + p * 4;
    asm volatile("red.global.add.v4.f32 [%0], {%1, %2, %3, %4};"
                 :: "l"(ap), "f"(v.x * w), "f"(v.y * w), "f"(v.z * w), "f"(v.w * w)
                 : "memory");
}

// ---------------- SortPool: per-graph top-K desc by last channel -----------
// key packs (ordered float, rank) so ties break by original index (stable,
// matching jnp.lexsort). Capacity 512 >> max graph size (mean 128, sd ~11).
__global__ void __launch_bounds__(256) k_sortpool(
    const float* __restrict__ gamma, const float* __restrict__ beta,
    const float* __restrict__ rmean, const float* __restrict__ rvar)
{
    __shared__ unsigned long long keys[CAP];
    __shared__ float ssc[HH], ssh[HH];
    __shared__ int ssel[KK];
    int b = blockIdx.x, t = threadIdx.x;
    if (t < HH) {
        int o = 2 * HH + t;  // layer-2 BN params
        float s = gamma[o] * rsqrtf(rvar[o] + EPSF);
        ssc[t] = s;
        ssh[t] = beta[o] - rmean[o] * s;
    }
    __syncthreads();

    int start = g_start[b];
    int cnt = g_cnt[b];
    int cc = min(cnt, CAP);
    float sc31 = ssc[31], sh31 = ssh[31];

    for (int r = t; r < CAP; r += 256) {
        unsigned long long key = 0xFFFFFFFFFFFFFFFFull;  // pad -> sorts last
        if (r < cc) {
            float a = g_agg[(size_t)(start + r) * HH + 31];
            float v = fmaxf(fmaf(a, sc31, sh31), 0.f);
            unsigned u;
            if (v == 0.0f) u = 0x80000000u;  // canonicalize +-0
            else {
                u = __float_as_uint(v);
                u = (u & 0x80000000u) ? ~u : (u | 0x80000000u);
            }
            // ascending sort key: smaller = larger value; ties -> smaller rank
            key = ((unsigned long long)(u ^ 0xFFFFFFFFu) << 32) | (unsigned)r;
        }
        keys[r] = key;
    }
    __syncthreads();

    // bitonic sort ascending, 512 elements, 256 threads
    for (int k = 2; k <= CAP; k <<= 1) {
        for (int j = k >> 1; j > 0; j >>= 1) {
            for (int base = 0; base < CAP; base += 256) {
                int i = base + t;
                int ixj = i ^ j;
                if (ixj > i) {
                    unsigned long long a = keys[i], c = keys[ixj];
                    bool up = ((i & k) == 0);
                    bool sw = up ? (a > c) : (a < c);
                    if (sw) { keys[i] = c; keys[ixj] = a; }
                }
            }
            __syncthreads();
        }
    }

    int nval = min(cc, KK);
    if (t < KK) {
        ssel[t] = (t < nval) ? (int)(unsigned)(keys[t] & 0xFFFFFFFFu) : -1;
    }
    __syncthreads();

    for (int idx = t; idx < KK * HH; idx += 256) {
        int k = idx >> 5, j = idx & 31;
        float v = 0.f;
        int r = ssel[k];
        if (r >= 0) {
            float a = g_agg[(size_t)(start + r) * HH + j];
            v = fmaxf(fmaf(a, ssc[j], ssh[j]), 0.f);
        }
        g_pooled[(size_t)b * (KK * HH) + idx] = v;
    }
}

// ---------------- MLP head: warp per graph ---------------------------------
__global__ void __launch_bounds__(256) k_mlp(
    const float* __restrict__ W1, const float* __restrict__ b1,
    const float* __restrict__ W2, const float* __restrict__ b2,
    const float* __restrict__ W3, const float* __restrict__ b3,
    float* __restrict__ out)
{
    int gwarp = (blockIdx.x * 256 + threadIdx.x) >> 5;  // graph id, 4096 warps
    int lane = threadIdx.x & 31;
    if (gwarp >= BB) return;

    const float* pr = g_pooled + (size_t)gwarp * (KK * HH);
    float acc = b1[lane];
    for (int p0 = 0; p0 < KK * HH; p0 += 32) {
        float xv = pr[p0 + lane];
#pragma unroll
        for (int jj = 0; jj < 32; jj++) {
            float xs = __shfl_sync(0xffffffffu, xv, jj);
            acc = fmaf(xs, W1[(p0 + jj) * 32 + lane], acc);
        }
    }
    float h1 = fmaxf(acc, 0.f);

    float pm[16];
#pragma unroll
    for (int m = 0; m < 16; m++) pm[m] = h1 * W2[lane * 16 + m];
#pragma unroll
    for (int off = 16; off; off >>= 1) {
#pragma unroll
        for (int m = 0; m < 16; m++) pm[m] += __shfl_xor_sync(0xffffffffu, pm[m], off);
    }
    float o = b3[0];
#pragma unroll
    for (int m = 0; m < 16; m++) o = fmaf(fmaxf(pm[m] + b2[m], 0.f), W3[m], o);
    if (lane == 0) out[gwarp] = o;
}

// ---------------- launch ----------------------------------------------------
extern "C" void kernel_launch(void* const* d_in, const int* in_sizes, int n_in,
                              void* d_out, int out_size) {
    const int*   xz    = (const int*)d_in[0];
    const int*   ei    = (const int*)d_in[1];
    const int*   batch = (const int*)d_in[2];
    const float* emb   = (const float*)d_in[3];
    const float* Wc    = (const float*)d_in[4];
    const float* bc    = (const float*)d_in[5];
    const float* gamma = (const float*)d_in[6];
    const float* beta  = (const float*)d_in[7];
    const float* rmean = (const float*)d_in[8];
    const float* rvar  = (const float*)d_in[9];
    const float* W1    = (const float*)d_in[10];
    const float* b1    = (const float*)d_in[11];
    const float* W2    = (const float*)d_in[12];
    const float* b2    = (const float*)d_in[13];
    const float* W3    = (const float*)d_in[14];
    const float* b3    = (const float*)d_in[15];
    float* out = (float*)d_out;

    const int* src = ei;
    const int* dst = ei + EE;

    k_zero<<<NN / 256, 256>>>();
    k_degcnt<<<EE / 256, 256>>>(dst, batch);
    k_dinv<<<NN / 256, 256>>>();
    k_scan<<<1, 1024>>>();
    for (int l = 0; l < 3; l++) {
        k_gemm<<<NN / 256, 256>>>(l, Wc, bc, gamma, beta, rmean, rvar, emb, xz);
        k_edge<<<(EE * 8) / 256, 256>>>(src, dst);
    }
    k_sortpool<<<BB, 256>>>(gamma, beta, rmean, rvar);
    k_mlp<<<BB / 8, 256>>>(W1, b1, W2, b2, W3, b3, out);
}

// round 2
// speedup vs baseline: 1.2925x; 1.2925x over previous
#include <cuda_runtime.h>

#define NN 524288
#define EE 4194304
#define BB 4096
#define HH 32
#define KK 30
#define CAP 512
#define EPSF 1e-5f
#define NBLK 2048          // NN/256

// ---------------- scratch (device globals; no allocation allowed) ----------
__device__ int   g_deg[NN];
__device__ float g_dinv[NN];
__device__ float g_h[(size_t)NN * HH];
__device__ float g_agg[(size_t)NN * HH];
__device__ int   g_rowstart[NN + 1];
__device__ int   g_cursor[NN];
__device__ int2  g_csr[EE];          // (src, enorm bits)
__device__ int   g_bsum[NBLK];
__device__ int   g_start2[BB + 1];   // graph start offsets (batch is sorted)
__device__ float g_pooled[(size_t)BB * KK * HH];

// ---------------- setup -----------------------------------------------------
__global__ void k_zero() {
    int i = blockIdx.x * 256 + threadIdx.x;
    g_deg[i] = 0;
}

// in-degree histogram + graph-boundary detection (batch sorted)
__global__ void k_degb(const int* __restrict__ dst, const int* __restrict__ batch) {
    int i = blockIdx.x * 256 + threadIdx.x;   // grid covers EE
    atomicAdd(&g_deg[dst[i]], 1);
    if (i < NN) {
        int b1 = batch[i];
        int b0 = (i > 0) ? batch[i - 1] : -1;
        for (int b = b0 + 1; b <= b1; b++) g_start2[b] = i;
        if (i == NN - 1)
            for (int b = b1 + 1; b <= BB; b++) g_start2[b] = NN;
    }
}

__global__ void k_dinv() {
    int i = blockIdx.x * 256 + threadIdx.x;
    g_dinv[i] = rsqrtf((float)g_deg[i] + 1.0f);
}

// ---------------- exclusive scan of g_deg -> g_rowstart / g_cursor ---------
__global__ void k_scan1() {   // block partial sums
    __shared__ int s[256];
    int t = threadIdx.x;
    s[t] = g_deg[blockIdx.x * 256 + t];
    __syncthreads();
    for (int off = 128; off; off >>= 1) {
        if (t < off) s[t] += s[t + off];
        __syncthreads();
    }
    if (t == 0) g_bsum[blockIdx.x] = s[0];
}

__global__ void k_scan2() {   // exclusive scan of g_bsum[2048] (1 block, 1024 thr)
    __shared__ int s[1024];
    int t = threadIdx.x;
    int a = g_bsum[2 * t], b = g_bsum[2 * t + 1];
    int sum = a + b;
    s[t] = sum;
    __syncthreads();
    for (int off = 1; off < 1024; off <<= 1) {
        int v = (t >= off) ? s[t - off] : 0;
        __syncthreads();
        s[t] += v;
        __syncthreads();
    }
    int excl = s[t] - sum;
    g_bsum[2 * t] = excl;
    g_bsum[2 * t + 1] = excl + a;
}

__global__ void k_scan3() {   // per-element exclusive scan + block offset
    __shared__ int s[256];
    int t = threadIdx.x;
    int i = blockIdx.x * 256 + t;
    int d = g_deg[i];
    s[t] = d;
    __syncthreads();
    for (int off = 1; off < 256; off <<= 1) {
        int v = (t >= off) ? s[t - off] : 0;
        __syncthreads();
        s[t] += v;
        __syncthreads();
    }
    int excl = s[t] - d + g_bsum[blockIdx.x];
    g_rowstart[i] = excl;
    g_cursor[i] = excl;
    if (i == NN - 1) g_rowstart[NN] = EE;
}

// ---------------- CSR fill: slot = (src, enorm) ----------------------------
__global__ void k_fill(const int* __restrict__ src, const int* __restrict__ dst) {
    int e = blockIdx.x * 256 + threadIdx.x;   // grid covers EE
    int s = src[e], d = dst[e];
    float w = g_dinv[s] * g_dinv[d];
    int pos = atomicAdd(&g_cursor[d], 1);
    g_csr[pos] = make_int2(s, __float_as_int(w));
}

// ---------------- fused (BN+ReLU prev) + GEMM + agg init -------------------
__global__ void __launch_bounds__(256) k_gemm(
    int layer,
    const float* __restrict__ Wc, const float* __restrict__ bcp,
    const float* __restrict__ gamma, const float* __restrict__ beta,
    const float* __restrict__ rmean, const float* __restrict__ rvar,
    const float* __restrict__ emb, const int* __restrict__ xz)
{
    __shared__ float4 Ws4[HH * 8];
    __shared__ float ssc[HH], ssh[HH], sbc[HH];
    int t = threadIdx.x;
    {
        const float* wsrc = Wc + layer * HH * HH;
        if (t < HH * 8) Ws4[t] = ((const float4*)wsrc)[t];
    }
    if (t < HH) {
        sbc[t] = bcp[layer * HH + t];
        if (layer > 0) {
            int o = (layer - 1) * HH + t;
            float s = gamma[o] * rsqrtf(rvar[o] + EPSF);
            ssc[t] = s;
            ssh[t] = beta[o] - rmean[o] * s;
        }
    }
    __syncthreads();

    int n = blockIdx.x * 256 + t;
    float xin[HH];
    if (layer == 0) {
        const float4* ep = (const float4*)(emb + (size_t)xz[n] * HH);
#pragma unroll
        for (int q = 0; q < 8; q++) {
            float4 v = ep[q];
            xin[4 * q + 0] = v.x; xin[4 * q + 1] = v.y;
            xin[4 * q + 2] = v.z; xin[4 * q + 3] = v.w;
        }
    } else {
        const float4* ap = (const float4*)(g_agg + (size_t)n * HH);
#pragma unroll
        for (int q = 0; q < 8; q++) {
            float4 v = __ldcs(ap + q);
            xin[4 * q + 0] = fmaxf(fmaf(v.x, ssc[4 * q + 0], ssh[4 * q + 0]), 0.f);
            xin[4 * q + 1] = fmaxf(fmaf(v.y, ssc[4 * q + 1], ssh[4 * q + 1]), 0.f);
            xin[4 * q + 2] = fmaxf(fmaf(v.z, ssc[4 * q + 2], ssh[4 * q + 2]), 0.f);
            xin[4 * q + 3] = fmaxf(fmaf(v.w, ssc[4 * q + 3], ssh[4 * q + 3]), 0.f);
        }
    }

    float4 out[8];
#pragma unroll
    for (int q = 0; q < 8; q++) out[q] = make_float4(0.f, 0.f, 0.f, 0.f);
#pragma unroll
    for (int k = 0; k < HH; k++) {
        float xk = xin[k];
#pragma unroll
        for (int q = 0; q < 8; q++) {
            float4 w4 = Ws4[k * 8 + q];
            out[q].x = fmaf(xk, w4.x, out[q].x);
            out[q].y = fmaf(xk, w4.y, out[q].y);
            out[q].z = fmaf(xk, w4.z, out[q].z);
            out[q].w = fmaf(xk, w4.w, out[q].w);
        }
    }

    float dn = g_dinv[n];
    float sn = dn * dn;
    float4* hp  = (float4*)(g_h   + (size_t)n * HH);
    float4* ap2 = (float4*)(g_agg + (size_t)n * HH);
#pragma unroll
    for (int q = 0; q < 8; q++) {
        hp[q] = out[q];
        float4 av;
        av.x = fmaf(out[q].x, sn, sbc[4 * q + 0]);
        av.y = fmaf(out[q].y, sn, sbc[4 * q + 1]);
        av.z = fmaf(out[q].z, sn, sbc[4 * q + 2]);
        av.w = fmaf(out[q].w, sn, sbc[4 * q + 3]);
        __stcs(ap2 + q, av);
    }
}

// ---------------- pull aggregation: agg[n] += sum_e enorm * h[src_e] -------
// 8 threads per node, one float4 chunk each.
__global__ void __launch_bounds__(256) k_gather() {
    int tid = blockIdx.x * 256 + threadIdx.x;   // grid covers NN*8
    int n = tid >> 3;
    int p = tid & 7;
    int beg = g_rowstart[n];
    int end = g_rowstart[n + 1];
    float4* ap = (float4*)(g_agg + (size_t)n * HH) + p;
    float4 acc = __ldcs(ap);
    for (int r = beg; r < end; r++) {
        int2 ed = __ldcs(&g_csr[r]);
        float w = __int_as_float(ed.y);
        float4 hv = __ldg((const float4*)(g_h + (size_t)ed.x * HH) + p);
        acc.x = fmaf(hv.x, w, acc.x);
        acc.y = fmaf(hv.y, w, acc.y);
        acc.z = fmaf(hv.z, w, acc.z);
        acc.w = fmaf(hv.w, w, acc.w);
    }
    __stcs(ap, acc);
}

// ---------------- SortPool -------------------------------------------------
__global__ void __launch_bounds__(256) k_sortpool(
    const float* __restrict__ gamma, const float* __restrict__ beta,
    const float* __restrict__ rmean, const float* __restrict__ rvar)
{
    __shared__ unsigned long long keys[CAP];
    __shared__ float ssc[HH], ssh[HH];
    __shared__ int ssel[KK];
    int b = blockIdx.x, t = threadIdx.x;
    if (t < HH) {
        int o = 2 * HH + t;
        float s = gamma[o] * rsqrtf(rvar[o] + EPSF);
        ssc[t] = s;
        ssh[t] = beta[o] - rmean[o] * s;
    }
    __syncthreads();

    int start = g_start2[b];
    int cnt = g_start2[b + 1] - start;
    int cc = min(cnt, CAP);
    float sc31 = ssc[31], sh31 = ssh[31];

    for (int r = t; r < CAP; r += 256) {
        unsigned long long key = 0xFFFFFFFFFFFFFFFFull;
        if (r < cc) {
            float a = g_agg[(size_t)(start + r) * HH + 31];
            float v = fmaxf(fmaf(a, sc31, sh31), 0.f);
            unsigned u;
            if (v == 0.0f) u = 0x80000000u;
            else {
                u = __float_as_uint(v);
                u = (u & 0x80000000u) ? ~u : (u | 0x80000000u);
            }
            key = ((unsigned long long)(u ^ 0xFFFFFFFFu) << 32) | (unsigned)r;
        }
        keys[r] = key;
    }
    __syncthreads();

    for (int k = 2; k <= CAP; k <<= 1) {
        for (int j = k >> 1; j > 0; j >>= 1) {
            for (int base = 0; base < CAP; base += 256) {
                int i = base + t;
                int ixj = i ^ j;
                if (ixj > i) {
                    unsigned long long a = keys[i], c = keys[ixj];
                    bool up = ((i & k) == 0);
                    bool sw = up ? (a > c) : (a < c);
                    if (sw) { keys[i] = c; keys[ixj] = a; }
                }
            }
            __syncthreads();
        }
    }

    int nval = min(cc, KK);
    if (t < KK) ssel[t] = (t < nval) ? (int)(unsigned)(keys[t] & 0xFFFFFFFFu) : -1;
    __syncthreads();

    for (int idx = t; idx < KK * HH; idx += 256) {
        int k = idx >> 5, j = idx & 31;
        float v = 0.f;
        int r = ssel[k];
        if (r >= 0) {
            float a = g_agg[(size_t)(start + r) * HH + j];
            v = fmaxf(fmaf(a, ssc[j], ssh[j]), 0.f);
        }
        g_pooled[(size_t)b * (KK * HH) + idx] = v;
    }
}

// ---------------- MLP head: warp per graph ---------------------------------
__global__ void __launch_bounds__(256) k_mlp(
    const float* __restrict__ W1, const float* __restrict__ b1,
    const float* __restrict__ W2, const float* __restrict__ b2,
    const float* __restrict__ W3, const float* __restrict__ b3,
    float* __restrict__ out)
{
    int gwarp = (blockIdx.x * 256 + threadIdx.x) >> 5;
    int lane = threadIdx.x & 31;
    if (gwarp >= BB) return;

    const float* pr = g_pooled + (size_t)gwarp * (KK * HH);
    float acc = b1[lane];
    for (int p0 = 0; p0 < KK * HH; p0 += 32) {
        float xv = pr[p0 + lane];
#pragma unroll
        for (int jj = 0; jj < 32; jj++) {
            float xs = __shfl_sync(0xffffffffu, xv, jj);
            acc = fmaf(xs, W1[(p0 + jj) * 32 + lane], acc);
        }
    }
    float h1 = fmaxf(acc, 0.f);

    float pm[16];
#pragma unroll
    for (int m = 0; m < 16; m++) pm[m] = h1 * W2[lane * 16 + m];
#pragma unroll
    for (int off = 16; off; off >>= 1) {
#pragma unroll
        for (int m = 0; m < 16; m++) pm[m] += __shfl_xor_sync(0xffffffffu, pm[m], off);
    }
    float o = b3[0];
#pragma unroll
    for (int m = 0; m < 16; m++) o = fmaf(fmaxf(pm[m] + b2[m], 0.f), W3[m], o);
    if (lane == 0) out[gwarp] = o;
}

// ---------------- launch ----------------------------------------------------
extern "C" void kernel_launch(void* const* d_in, const int* in_sizes, int n_in,
                              void* d_out, int out_size) {
    const int*   xz    = (const int*)d_in[0];
    const int*   ei    = (const int*)d_in[1];
    const int*   batch = (const int*)d_in[2];
    const float* emb   = (const float*)d_in[3];
    const float* Wc    = (const float*)d_in[4];
    const float* bc    = (const float*)d_in[5];
    const float* gamma = (const float*)d_in[6];
    const float* beta  = (const float*)d_in[7];
    const float* rmean = (const float*)d_in[8];
    const float* rvar  = (const float*)d_in[9];
    const float* W1    = (const float*)d_in[10];
    const float* b1    = (const float*)d_in[11];
    const float* W2    = (const float*)d_in[12];
    const float* b2    = (const float*)d_in[13];
    const float* W3    = (const float*)d_in[14];
    const float* b3    = (const float*)d_in[15];
    float* out = (float*)d_out;

    const int* src = ei;
    const int* dst = ei + EE;

    k_zero<<<NBLK, 256>>>();
    k_degb<<<EE / 256, 256>>>(dst, batch);
    k_dinv<<<NBLK, 256>>>();
    k_scan1<<<NBLK, 256>>>();
    k_scan2<<<1, 1024>>>();
    k_scan3<<<NBLK, 256>>>();
    k_fill<<<EE / 256, 256>>>(src, dst);
    for (int l = 0; l < 3; l++) {
        k_gemm<<<NBLK, 256>>>(l, Wc, bc, gamma, beta, rmean, rvar, emb, xz);
        k_gather<<<(NN * 8) / 256, 256>>>();
    }
    k_sortpool<<<BB, 256>>>(gamma, beta, rmean, rvar);
    k_mlp<<<BB / 8, 256>>>(W1, b1, W2, b2, W3, b3, out);
}